// round 1
// baseline (speedup 1.0000x reference)
#include <cuda_runtime.h>
#include <math.h>

// Problem constants
#define DIMC   128
#define NWIN   49
#define HEADS  4
#define HD     32
#define NB     4096
#define NMASK  64
#define M_TOTAL (NB * NWIN)        // 200704 = 3136 * 64

// Scratch (allocation-free rule: static device globals)
__device__ float g_qkv[(size_t)NB * NWIN * 384];   // [M, 384] : q|k|v per row
__device__ float g_att[(size_t)NB * NWIN * DIMC];  // [M, 128] : attention output

// ---------------------------------------------------------------------------
// Tiled fp32 GEMM:  C[M][NC] = A[M][128] * W[NC][128]^T + bias
// 64x64 block tile, 256 threads, 4x4 micro-tile, K split into 2 chunks of 64.
// XOR swizzle on smem (float4-group index ^ (row>>3)&7) keeps the inner loop
// conflict-light so the kernel stays FFMA-bound rather than LDS-bound.
// ---------------------------------------------------------------------------
template<int NC>
__global__ __launch_bounds__(256) void gemm_bias_kernel(
    const float* __restrict__ A, const float* __restrict__ W,
    const float* __restrict__ bias, float* __restrict__ C)
{
    __shared__ float As[64][64];
    __shared__ float Ws[64][64];

    const int tid = threadIdx.x;
    const int m0  = blockIdx.x * 64;
    const int n0  = blockIdx.y * 64;
    const int tx  = tid & 15;     // n direction
    const int ty  = tid >> 4;     // m direction

    float acc[4][4] = {};

    #pragma unroll
    for (int kc = 0; kc < 2; kc++) {
        if (kc) __syncthreads();   // protect smem from previous chunk's readers

        // Load 64x64 chunk of A and W tiles (each thread: 4 float4 per tile)
        #pragma unroll
        for (int p = 0; p < 4; p++) {
            int r   = ty + p * 16;
            int key = (r >> 3) & 7;
            int col = 4 * (tx ^ key);
            *(float4*)&As[r][col] =
                *(const float4*)(A + (size_t)(m0 + r) * 128 + kc * 64 + tx * 4);
            *(float4*)&Ws[r][col] =
                *(const float4*)(W + (size_t)(n0 + r) * 128 + kc * 64 + tx * 4);
        }
        __syncthreads();

        #pragma unroll
        for (int kv = 0; kv < 16; kv++) {
            float4 a[4], w[4];
            #pragma unroll
            for (int i = 0; i < 4; i++) {
                int r = ty * 4 + i;
                a[i] = *(const float4*)&As[r][4 * (kv ^ ((r >> 3) & 7))];
            }
            #pragma unroll
            for (int j = 0; j < 4; j++) {
                int r = tx * 4 + j;
                w[j] = *(const float4*)&Ws[r][4 * (kv ^ ((r >> 3) & 7))];
            }
            #pragma unroll
            for (int i = 0; i < 4; i++)
                #pragma unroll
                for (int j = 0; j < 4; j++) {
                    acc[i][j] += a[i].x * w[j].x;
                    acc[i][j] += a[i].y * w[j].y;
                    acc[i][j] += a[i].z * w[j].z;
                    acc[i][j] += a[i].w * w[j].w;
                }
        }
    }

    float bv[4];
    #pragma unroll
    for (int j = 0; j < 4; j++) bv[j] = bias[n0 + tx * 4 + j];

    #pragma unroll
    for (int i = 0; i < 4; i++) {
        float4 o = make_float4(acc[i][0] + bv[0], acc[i][1] + bv[1],
                               acc[i][2] + bv[2], acc[i][3] + bv[3]);
        *(float4*)&C[(size_t)(m0 + ty * 4 + i) * NC + n0 + tx * 4] = o;
    }
}

// ---------------------------------------------------------------------------
// Fused per-(window, head) attention.
// Block = (b, h). Loads Q,K,V [49x32] into swizzled smem, builds
// S = scale*QK^T + rel_bias + shift_mask in smem, row softmax, then P*V.
// Writes g_att[(b*49+i)*128 + h*32 + d] (the transpose(0,2,1,3) layout).
// ---------------------------------------------------------------------------
__global__ __launch_bounds__(128) void attn_kernel(
    const float* __restrict__ qkv, const float* __restrict__ mask,
    const float* __restrict__ bias_table, const int* __restrict__ rel_index,
    float* __restrict__ outp)
{
    __shared__ float qs[49][36];
    __shared__ float ks[49][36];
    __shared__ float vs[49][36];
    __shared__ float S[49][49];

    const int tid = threadIdx.x;
    const int b   = blockIdx.x >> 2;
    const int h   = blockIdx.x & 3;
    const float scale = 0.17677669529663687f;   // 32^-0.5

    // Load q/k/v for this (window, head). Swizzled: group = (d>>2) ^ ((i>>3)&7)
    for (int t = tid; t < NWIN * HD; t += 128) {
        int i = t >> 5, d = t & 31;
        size_t row = ((size_t)b * NWIN + i) * 384 + h * HD + d;
        int c = 4 * ((d >> 2) ^ ((i >> 3) & 7)) + (d & 3);
        qs[i][c] = qkv[row];
        ks[i][c] = qkv[row + 128];
        vs[i][c] = qkv[row + 256];
    }
    // S <- relative-position bias + shifted-window mask
    for (int t = tid; t < NWIN * NWIN; t += 128) {
        (&S[0][0])[t] = bias_table[rel_index[t] * HEADS + h]
                      + mask[(size_t)(b & 63) * (NWIN * NWIN) + t];
    }
    __syncthreads();

    // S += scale * Q K^T
    for (int t = tid; t < NWIN * NWIN; t += 128) {
        int i = t / 49, j = t - i * 49;
        int ki = (i >> 3) & 7, kj = (j >> 3) & 7;
        float s = 0.f;
        #pragma unroll
        for (int d4 = 0; d4 < 8; d4++) {
            float4 a  = *(const float4*)&qs[i][4 * (d4 ^ ki)];
            float4 bq = *(const float4*)&ks[j][4 * (d4 ^ kj)];
            s += a.x * bq.x + a.y * bq.y + a.z * bq.z + a.w * bq.w;
        }
        (&S[0][0])[t] += s * scale;
    }
    __syncthreads();

    // Row softmax (49 rows, one thread each)
    if (tid < NWIN) {
        float mx = -1e30f;
        #pragma unroll 7
        for (int j = 0; j < NWIN; j++) mx = fmaxf(mx, S[tid][j]);
        float sum = 0.f;
        #pragma unroll 7
        for (int j = 0; j < NWIN; j++) {
            float e = __expf(S[tid][j] - mx);
            S[tid][j] = e;
            sum += e;
        }
        float inv = 1.f / sum;
        #pragma unroll 7
        for (int j = 0; j < NWIN; j++) S[tid][j] *= inv;
    }
    __syncthreads();

    // O = P * V   (task = (i, d4) -> one float4 of the output row)
    for (int t = tid; t < NWIN * (HD / 4); t += 128) {
        int i = t >> 3, d4 = t & 7;
        float4 acc = make_float4(0.f, 0.f, 0.f, 0.f);
        #pragma unroll 7
        for (int j = 0; j < NWIN; j++) {
            float p  = S[i][j];
            float4 v = *(const float4*)&vs[j][4 * (d4 ^ ((j >> 3) & 7))];
            acc.x += p * v.x; acc.y += p * v.y;
            acc.z += p * v.z; acc.w += p * v.w;
        }
        *(float4*)(outp + ((size_t)b * NWIN + i) * DIMC + h * HD + d4 * 4) = acc;
    }
}

// ---------------------------------------------------------------------------
extern "C" void kernel_launch(void* const* d_in, const int* in_sizes, int n_in,
                              void* d_out, int out_size)
{
    const float* x          = (const float*)d_in[0];
    const float* mask       = (const float*)d_in[1];
    const float* qkv_w      = (const float*)d_in[2];
    const float* qkv_b      = (const float*)d_in[3];
    const float* proj_w     = (const float*)d_in[4];
    const float* proj_b     = (const float*)d_in[5];
    const float* bias_table = (const float*)d_in[6];
    const int*   rel_index  = (const int*)d_in[7];
    float*       out        = (float*)d_out;

    float *qkvbuf = nullptr, *attbuf = nullptr;
    cudaGetSymbolAddress((void**)&qkvbuf, g_qkv);
    cudaGetSymbolAddress((void**)&attbuf, g_att);

    dim3 g1(M_TOTAL / 64, 384 / 64);
    gemm_bias_kernel<384><<<g1, 256>>>(x, qkv_w, qkv_b, qkvbuf);

    attn_kernel<<<NB * HEADS, 128>>>(qkvbuf, mask, bias_table, rel_index, attbuf);

    dim3 g3(M_TOTAL / 64, DIMC / 64);
    gemm_bias_kernel<DIMC><<<g3, 256>>>(attbuf, proj_w, proj_b, out);
}

// round 2
// speedup vs baseline: 1.6350x; 1.6350x over previous
#include <cuda_runtime.h>
#include <math.h>
#include <stdint.h>

// Problem constants
#define DIMC   128
#define NWIN   49
#define HEADS  4
#define HD     32
#define NB     4096
#define M_TOTAL (NB * NWIN)        // 200704 = 1568 * 128

// Scratch (allocation-free rule: static device globals)
__device__ float g_qkv[(size_t)NB * NWIN * 384];   // [M, 384] : q|k|v per row
__device__ float g_att[(size_t)NB * NWIN * DIMC];  // [M, 128] : attention output

__device__ __forceinline__ float to_tf32(float x) {
    float r;
    asm("cvt.rna.tf32.f32 %0, %1;" : "=f"(r) : "f"(x));
    return r;
}

__device__ __forceinline__ void mma_tf32(float c[4], const uint32_t a[4],
                                         uint32_t b0, uint32_t b1) {
    asm volatile(
        "mma.sync.aligned.m16n8k8.row.col.f32.tf32.tf32.f32 "
        "{%0,%1,%2,%3}, {%4,%5,%6,%7}, {%8,%9}, {%0,%1,%2,%3};"
        : "+f"(c[0]), "+f"(c[1]), "+f"(c[2]), "+f"(c[3])
        : "r"(a[0]), "r"(a[1]), "r"(a[2]), "r"(a[3]), "r"(b0), "r"(b1));
}

// ---------------------------------------------------------------------------
// Tensor-core tf32 GEMM:  C[M][NC] = A[M][128] * W[NC][128]^T + bias
// 128x64 block tile, 256 threads (8 warps: 4m x 2n), warp tile 32x32
// (2x4 m16n8k8 tiles). K chunked by 32.
// smem layout: k-interleaved within 8-groups (pos(c) = ((c&3)<<1)|(c>>2)),
// row stride 40 floats -> all fragment loads are conflict-free LDS.64.
// ---------------------------------------------------------------------------
template<int NC>
__global__ __launch_bounds__(256) void gemm_tc_kernel(
    const float* __restrict__ A, const float* __restrict__ W,
    const float* __restrict__ bias, float* __restrict__ C)
{
    __shared__ float As[128][40];
    __shared__ float Ws[64][40];

    const int tid  = threadIdx.x;
    const int lane = tid & 31;
    const int warp = tid >> 5;
    const int wm   = warp & 3;           // 0..3 (m direction)
    const int wn   = warp >> 2;          // 0..1 (n direction)
    const int g    = lane >> 2;          // groupID 0..7
    const int t    = lane & 3;           // threadID-in-group 0..3
    const long m0  = (long)blockIdx.x * 128;
    const int  n0  = blockIdx.y * 64;

    float acc[2][4][4] = {};             // [mtile][ntile][frag]

    #pragma unroll
    for (int kc = 0; kc < 4; kc++) {
        if (kc) __syncthreads();

        // Stage A chunk [128 x 32] with tf32 rounding + k-interleave
        #pragma unroll
        for (int p = 0; p < 4; p++) {
            int q  = tid + p * 256;
            int r  = q >> 3;
            int f4 = q & 7;
            float4 v = *(const float4*)(A + (m0 + r) * 128 + kc * 32 + f4 * 4);
            int base = (f4 >> 1) * 8 + (f4 & 1);
            As[r][base + 0] = to_tf32(v.x);
            As[r][base + 2] = to_tf32(v.y);
            As[r][base + 4] = to_tf32(v.z);
            As[r][base + 6] = to_tf32(v.w);
        }
        // Stage W chunk [64 x 32]
        #pragma unroll
        for (int p = 0; p < 2; p++) {
            int q  = tid + p * 256;
            int r  = q >> 3;
            int f4 = q & 7;
            float4 v = *(const float4*)(W + (size_t)(n0 + r) * 128 + kc * 32 + f4 * 4);
            int base = (f4 >> 1) * 8 + (f4 & 1);
            Ws[r][base + 0] = to_tf32(v.x);
            Ws[r][base + 2] = to_tf32(v.y);
            Ws[r][base + 4] = to_tf32(v.z);
            Ws[r][base + 6] = to_tf32(v.w);
        }
        __syncthreads();

        #pragma unroll
        for (int s = 0; s < 4; s++) {
            const int off = s * 8 + 2 * t;
            uint32_t a[2][4];
            #pragma unroll
            for (int mt = 0; mt < 2; mt++) {
                int r = wm * 32 + mt * 16 + g;
                float2 f0 = *(const float2*)&As[r][off];      // a0 (k=t), a2 (k=t+4)
                float2 f1 = *(const float2*)&As[r + 8][off];  // a1, a3
                a[mt][0] = __float_as_uint(f0.x);
                a[mt][1] = __float_as_uint(f1.x);
                a[mt][2] = __float_as_uint(f0.y);
                a[mt][3] = __float_as_uint(f1.y);
            }
            #pragma unroll
            for (int nt = 0; nt < 4; nt++) {
                int n = wn * 32 + nt * 8 + g;
                float2 fb = *(const float2*)&Ws[n][off];      // b0 (k=t), b1 (k=t+4)
                uint32_t b0 = __float_as_uint(fb.x);
                uint32_t b1 = __float_as_uint(fb.y);
                #pragma unroll
                for (int mt = 0; mt < 2; mt++)
                    mma_tf32(acc[mt][nt], a[mt], b0, b1);
            }
        }
    }

    // Epilogue: c0 (g, 2t), c1 (g, 2t+1), c2 (g+8, 2t), c3 (g+8, 2t+1)
    #pragma unroll
    for (int nt = 0; nt < 4; nt++) {
        int col = n0 + wn * 32 + nt * 8 + 2 * t;
        float b0 = bias[col], b1 = bias[col + 1];
        #pragma unroll
        for (int mt = 0; mt < 2; mt++) {
            long r = m0 + wm * 32 + mt * 16 + g;
            float2 o0 = make_float2(acc[mt][nt][0] + b0, acc[mt][nt][1] + b1);
            float2 o1 = make_float2(acc[mt][nt][2] + b0, acc[mt][nt][3] + b1);
            *(float2*)&C[r * NC + col]       = o0;
            *(float2*)&C[(r + 8) * NC + col] = o1;
        }
    }
}

// ---------------------------------------------------------------------------
// Fused per-(window, head) attention (unchanged from round 0).
// ---------------------------------------------------------------------------
__global__ __launch_bounds__(128) void attn_kernel(
    const float* __restrict__ qkv, const float* __restrict__ mask,
    const float* __restrict__ bias_table, const int* __restrict__ rel_index,
    float* __restrict__ outp)
{
    __shared__ float qs[49][36];
    __shared__ float ks[49][36];
    __shared__ float vs[49][36];
    __shared__ float S[49][49];

    const int tid = threadIdx.x;
    const int b   = blockIdx.x >> 2;
    const int h   = blockIdx.x & 3;
    const float scale = 0.17677669529663687f;   // 32^-0.5

    for (int t = tid; t < NWIN * HD; t += 128) {
        int i = t >> 5, d = t & 31;
        size_t row = ((size_t)b * NWIN + i) * 384 + h * HD + d;
        int c = 4 * ((d >> 2) ^ ((i >> 3) & 7)) + (d & 3);
        qs[i][c] = qkv[row];
        ks[i][c] = qkv[row + 128];
        vs[i][c] = qkv[row + 256];
    }
    for (int t = tid; t < NWIN * NWIN; t += 128) {
        (&S[0][0])[t] = bias_table[rel_index[t] * HEADS + h]
                      + mask[(size_t)(b & 63) * (NWIN * NWIN) + t];
    }
    __syncthreads();

    for (int t = tid; t < NWIN * NWIN; t += 128) {
        int i = t / 49, j = t - i * 49;
        int ki = (i >> 3) & 7, kj = (j >> 3) & 7;
        float s = 0.f;
        #pragma unroll
        for (int d4 = 0; d4 < 8; d4++) {
            float4 a  = *(const float4*)&qs[i][4 * (d4 ^ ki)];
            float4 bq = *(const float4*)&ks[j][4 * (d4 ^ kj)];
            s += a.x * bq.x + a.y * bq.y + a.z * bq.z + a.w * bq.w;
        }
        (&S[0][0])[t] += s * scale;
    }
    __syncthreads();

    if (tid < NWIN) {
        float mx = -1e30f;
        #pragma unroll 7
        for (int j = 0; j < NWIN; j++) mx = fmaxf(mx, S[tid][j]);
        float sum = 0.f;
        #pragma unroll 7
        for (int j = 0; j < NWIN; j++) {
            float e = __expf(S[tid][j] - mx);
            S[tid][j] = e;
            sum += e;
        }
        float inv = 1.f / sum;
        #pragma unroll 7
        for (int j = 0; j < NWIN; j++) S[tid][j] *= inv;
    }
    __syncthreads();

    for (int t = tid; t < NWIN * (HD / 4); t += 128) {
        int i = t >> 3, d4 = t & 7;
        float4 acc = make_float4(0.f, 0.f, 0.f, 0.f);
        #pragma unroll 7
        for (int j = 0; j < NWIN; j++) {
            float p  = S[i][j];
            float4 v = *(const float4*)&vs[j][4 * (d4 ^ ((j >> 3) & 7))];
            acc.x += p * v.x; acc.y += p * v.y;
            acc.z += p * v.z; acc.w += p * v.w;
        }
        *(float4*)(outp + ((size_t)b * NWIN + i) * DIMC + h * HD + d4 * 4) = acc;
    }
}

// ---------------------------------------------------------------------------
extern "C" void kernel_launch(void* const* d_in, const int* in_sizes, int n_in,
                              void* d_out, int out_size)
{
    const float* x          = (const float*)d_in[0];
    const float* mask       = (const float*)d_in[1];
    const float* qkv_w      = (const float*)d_in[2];
    const float* qkv_b      = (const float*)d_in[3];
    const float* proj_w     = (const float*)d_in[4];
    const float* proj_b     = (const float*)d_in[5];
    const float* bias_table = (const float*)d_in[6];
    const int*   rel_index  = (const int*)d_in[7];
    float*       out        = (float*)d_out;

    float *qkvbuf = nullptr, *attbuf = nullptr;
    cudaGetSymbolAddress((void**)&qkvbuf, g_qkv);
    cudaGetSymbolAddress((void**)&attbuf, g_att);

    dim3 g1(M_TOTAL / 128, 384 / 64);
    gemm_tc_kernel<384><<<g1, 256>>>(x, qkv_w, qkv_b, qkvbuf);

    attn_kernel<<<NB * HEADS, 128>>>(qkvbuf, mask, bias_table, rel_index, attbuf);

    dim3 g3(M_TOTAL / 128, DIMC / 64);
    gemm_tc_kernel<DIMC><<<g3, 256>>>(attbuf, proj_w, proj_b, out);
}

// round 3
// speedup vs baseline: 2.2197x; 1.3576x over previous
#include <cuda_runtime.h>
#include <math.h>
#include <stdint.h>

// Problem constants
#define DIMC   128
#define NWIN   49
#define HEADS  4
#define HD     32
#define NB     4096
#define M_TOTAL (NB * NWIN)        // 200704 = 1568 * 128

// Scratch (allocation-free rule: static device globals)
__device__ float g_qkv[(size_t)NB * NWIN * 384];   // [M, 384] : q|k|v per row
__device__ float g_att[(size_t)NB * NWIN * DIMC];  // [M, 128] : attention output

__device__ __forceinline__ float to_tf32(float x) {
    float r;
    asm("cvt.rna.tf32.f32 %0, %1;" : "=f"(r) : "f"(x));
    return r;
}

__device__ __forceinline__ void mma_tf32(float c[4], const uint32_t a[4],
                                         uint32_t b0, uint32_t b1) {
    asm volatile(
        "mma.sync.aligned.m16n8k8.row.col.f32.tf32.tf32.f32 "
        "{%0,%1,%2,%3}, {%4,%5,%6,%7}, {%8,%9}, {%0,%1,%2,%3};"
        : "+f"(c[0]), "+f"(c[1]), "+f"(c[2]), "+f"(c[3])
        : "r"(a[0]), "r"(a[1]), "r"(a[2]), "r"(a[3]), "r"(b0), "r"(b1));
}

// ---------------------------------------------------------------------------
// Tensor-core tf32 GEMM (unchanged from round 2):
// C[M][NC] = A[M][128] * W[NC][128]^T + bias
// ---------------------------------------------------------------------------
template<int NC>
__global__ __launch_bounds__(256) void gemm_tc_kernel(
    const float* __restrict__ A, const float* __restrict__ W,
    const float* __restrict__ bias, float* __restrict__ C)
{
    __shared__ float As[128][40];
    __shared__ float Ws[64][40];

    const int tid  = threadIdx.x;
    const int lane = tid & 31;
    const int warp = tid >> 5;
    const int wm   = warp & 3;
    const int wn   = warp >> 2;
    const int g    = lane >> 2;
    const int t    = lane & 3;
    const long m0  = (long)blockIdx.x * 128;
    const int  n0  = blockIdx.y * 64;

    float acc[2][4][4] = {};

    #pragma unroll
    for (int kc = 0; kc < 4; kc++) {
        if (kc) __syncthreads();

        #pragma unroll
        for (int p = 0; p < 4; p++) {
            int q  = tid + p * 256;
            int r  = q >> 3;
            int f4 = q & 7;
            float4 v = *(const float4*)(A + (m0 + r) * 128 + kc * 32 + f4 * 4);
            int base = (f4 >> 1) * 8 + (f4 & 1);
            As[r][base + 0] = to_tf32(v.x);
            As[r][base + 2] = to_tf32(v.y);
            As[r][base + 4] = to_tf32(v.z);
            As[r][base + 6] = to_tf32(v.w);
        }
        #pragma unroll
        for (int p = 0; p < 2; p++) {
            int q  = tid + p * 256;
            int r  = q >> 3;
            int f4 = q & 7;
            float4 v = *(const float4*)(W + (size_t)(n0 + r) * 128 + kc * 32 + f4 * 4);
            int base = (f4 >> 1) * 8 + (f4 & 1);
            Ws[r][base + 0] = to_tf32(v.x);
            Ws[r][base + 2] = to_tf32(v.y);
            Ws[r][base + 4] = to_tf32(v.z);
            Ws[r][base + 6] = to_tf32(v.w);
        }
        __syncthreads();

        #pragma unroll
        for (int s = 0; s < 4; s++) {
            const int off = s * 8 + 2 * t;
            uint32_t a[2][4];
            #pragma unroll
            for (int mt = 0; mt < 2; mt++) {
                int r = wm * 32 + mt * 16 + g;
                float2 f0 = *(const float2*)&As[r][off];
                float2 f1 = *(const float2*)&As[r + 8][off];
                a[mt][0] = __float_as_uint(f0.x);
                a[mt][1] = __float_as_uint(f1.x);
                a[mt][2] = __float_as_uint(f0.y);
                a[mt][3] = __float_as_uint(f1.y);
            }
            #pragma unroll
            for (int nt = 0; nt < 4; nt++) {
                int n = wn * 32 + nt * 8 + g;
                float2 fb = *(const float2*)&Ws[n][off];
                uint32_t b0 = __float_as_uint(fb.x);
                uint32_t b1 = __float_as_uint(fb.y);
                #pragma unroll
                for (int mt = 0; mt < 2; mt++)
                    mma_tf32(acc[mt][nt], a[mt], b0, b1);
            }
        }
    }

    #pragma unroll
    for (int nt = 0; nt < 4; nt++) {
        int col = n0 + wn * 32 + nt * 8 + 2 * t;
        float b0 = bias[col], b1 = bias[col + 1];
        #pragma unroll
        for (int mt = 0; mt < 2; mt++) {
            long r = m0 + wm * 32 + mt * 16 + g;
            float2 o0 = make_float2(acc[mt][nt][0] + b0, acc[mt][nt][1] + b1);
            float2 o1 = make_float2(acc[mt][nt][2] + b0, acc[mt][nt][3] + b1);
            *(float2*)&C[r * NC + col]       = o0;
            *(float2*)&C[(r + 8) * NC + col] = o1;
        }
    }
}

// ---------------------------------------------------------------------------
// Tensor-core attention. Block = (window b, head h), 128 threads = 4 warps.
// Warp w owns m-tile rows [16w, 16w+16). Padded: M 49->64, N(keys) 49->56.
//   S[64x56] = (Q*scale)[64x32] K[56x32]^T + bias + mask   (tf32 mma)
//   softmax rows (8 lanes/row, shfl reductions), P written in-place
//   k-interleaved, O[64x32] = P[64x56] Vt[32x56]^T         (tf32 mma)
// Pad cols get -1e30 pre-softmax -> P=0 there; pad rows are never stored.
// All smem row strides are == 8 (mod 32) floats -> fragment LDS.64 loads
// are phase-conflict-free.
// ---------------------------------------------------------------------------
__global__ __launch_bounds__(128) void attn_tc_kernel(
    const float* __restrict__ qkv, const float* __restrict__ mask,
    const float* __restrict__ bias_table, const int* __restrict__ rel_index,
    float* __restrict__ outp)
{
    __shared__ float Qs[64][40];
    __shared__ float Ks[56][40];
    __shared__ float Vt[32][72];
    __shared__ float Ss[64][72];

    const int tid  = threadIdx.x;
    const int lane = tid & 31;
    const int warp = tid >> 5;
    const int g = lane >> 2, t = lane & 3;
    const int b = blockIdx.x >> 2, h = blockIdx.x & 3;
    const float scale = 0.17677669529663687f;   // 32^-0.5

    // ---- stage Q (scaled), K, V^T with tf32 rounding + k-interleave ----
    for (int q = tid; q < 64 * 8; q += 128) {
        int i = q >> 3, f4 = q & 7;
        int base = (f4 >> 1) * 8 + (f4 & 1);
        if (i < 49) {
            size_t row = ((size_t)b * 49 + i) * 384 + h * 32 + f4 * 4;
            float4 vq = *(const float4*)(qkv + row);
            float4 vk = *(const float4*)(qkv + row + 128);
            float4 vv = *(const float4*)(qkv + row + 256);
            Qs[i][base + 0] = to_tf32(vq.x * scale);
            Qs[i][base + 2] = to_tf32(vq.y * scale);
            Qs[i][base + 4] = to_tf32(vq.z * scale);
            Qs[i][base + 6] = to_tf32(vq.w * scale);
            Ks[i][base + 0] = to_tf32(vk.x);
            Ks[i][base + 2] = to_tf32(vk.y);
            Ks[i][base + 4] = to_tf32(vk.z);
            Ks[i][base + 6] = to_tf32(vk.w);
            int pj = (i >> 3) * 8 + 2 * (i & 3) + ((i >> 2) & 1);
            Vt[f4 * 4 + 0][pj] = to_tf32(vv.x);
            Vt[f4 * 4 + 1][pj] = to_tf32(vv.y);
            Vt[f4 * 4 + 2][pj] = to_tf32(vv.z);
            Vt[f4 * 4 + 3][pj] = to_tf32(vv.w);
        } else {
            Qs[i][base] = Qs[i][base + 2] = Qs[i][base + 4] = Qs[i][base + 6] = 0.f;
            if (i < 56) {
                Ks[i][base] = Ks[i][base + 2] = Ks[i][base + 4] = Ks[i][base + 6] = 0.f;
                int pj = (i >> 3) * 8 + 2 * (i & 3) + ((i >> 2) & 1);
                Vt[f4 * 4 + 0][pj] = 0.f;
                Vt[f4 * 4 + 1][pj] = 0.f;
                Vt[f4 * 4 + 2][pj] = 0.f;
                Vt[f4 * 4 + 3][pj] = 0.f;
            }
        }
    }

    // ---- stage bias + shift mask into S (pad cols -1e30, pad rows 0) ----
    const float* mrow = mask + (size_t)(b & 63) * (NWIN * NWIN);
    for (int q2 = tid; q2 < 49 * 56; q2 += 128) {
        int i = q2 / 56, j = q2 - i * 56;
        Ss[i][j] = (j < 49)
            ? bias_table[rel_index[i * 49 + j] * HEADS + h] + mrow[i * 49 + j]
            : -1e30f;
    }
    for (int q2 = tid; q2 < 15 * 56; q2 += 128) {
        int i = 49 + q2 / 56, j = q2 % 56;
        Ss[i][j] = 0.f;
    }
    __syncthreads();

    // ---- S += (Q*scale) K^T ----
    const int r0 = warp * 16 + g;
    float c[7][4];
    #pragma unroll
    for (int nt = 0; nt < 7; nt++)
        #pragma unroll
        for (int e = 0; e < 4; e++) c[nt][e] = 0.f;

    #pragma unroll
    for (int s = 0; s < 4; s++) {
        const int off = s * 8 + 2 * t;
        uint32_t a[4];
        float2 f0 = *(const float2*)&Qs[r0][off];
        float2 f1 = *(const float2*)&Qs[r0 + 8][off];
        a[0] = __float_as_uint(f0.x); a[1] = __float_as_uint(f1.x);
        a[2] = __float_as_uint(f0.y); a[3] = __float_as_uint(f1.y);
        #pragma unroll
        for (int nt = 0; nt < 7; nt++) {
            float2 fb = *(const float2*)&Ks[nt * 8 + g][off];
            mma_tf32(c[nt], a, __float_as_uint(fb.x), __float_as_uint(fb.y));
        }
    }
    #pragma unroll
    for (int nt = 0; nt < 7; nt++) {
        int col = nt * 8 + 2 * t;
        Ss[r0][col]         += c[nt][0];
        Ss[r0][col + 1]     += c[nt][1];
        Ss[r0 + 8][col]     += c[nt][2];
        Ss[r0 + 8][col + 1] += c[nt][3];
    }
    __syncthreads();

    // ---- row softmax: 8 lanes per row; P written in-place, k-interleaved ----
    {
        const int l8  = tid & 7;
        const int rb  = tid >> 3;                       // 0..15
        const int pos = 2 * (l8 & 3) + (l8 >> 2);       // interleave of j&7
        #pragma unroll
        for (int rr = 0; rr < 4; rr++) {
            const int i = rb + rr * 16;
            float v[7];
            float mx = -1e30f;
            #pragma unroll
            for (int c2 = 0; c2 < 7; c2++) {
                v[c2] = Ss[i][l8 + 8 * c2];
                mx = fmaxf(mx, v[c2]);
            }
            mx = fmaxf(mx, __shfl_xor_sync(0xffffffffu, mx, 1, 8));
            mx = fmaxf(mx, __shfl_xor_sync(0xffffffffu, mx, 2, 8));
            mx = fmaxf(mx, __shfl_xor_sync(0xffffffffu, mx, 4, 8));
            float sum = 0.f;
            #pragma unroll
            for (int c2 = 0; c2 < 7; c2++) {
                v[c2] = __expf(v[c2] - mx);
                sum += v[c2];
            }
            sum += __shfl_xor_sync(0xffffffffu, sum, 1, 8);
            sum += __shfl_xor_sync(0xffffffffu, sum, 2, 8);
            sum += __shfl_xor_sync(0xffffffffu, sum, 4, 8);
            const float inv = 1.f / sum;
            #pragma unroll
            for (int c2 = 0; c2 < 7; c2++)
                Ss[i][c2 * 8 + pos] = to_tf32(v[c2] * inv);
        }
    }
    __syncthreads();

    // ---- O = P V ----
    float o[4][4];
    #pragma unroll
    for (int nt = 0; nt < 4; nt++)
        #pragma unroll
        for (int e = 0; e < 4; e++) o[nt][e] = 0.f;

    #pragma unroll
    for (int s = 0; s < 7; s++) {
        const int off = s * 8 + 2 * t;
        uint32_t a[4];
        float2 f0 = *(const float2*)&Ss[r0][off];
        float2 f1 = *(const float2*)&Ss[r0 + 8][off];
        a[0] = __float_as_uint(f0.x); a[1] = __float_as_uint(f1.x);
        a[2] = __float_as_uint(f0.y); a[3] = __float_as_uint(f1.y);
        #pragma unroll
        for (int nt = 0; nt < 4; nt++) {
            float2 fb = *(const float2*)&Vt[nt * 8 + g][off];
            mma_tf32(o[nt], a, __float_as_uint(fb.x), __float_as_uint(fb.y));
        }
    }

    #pragma unroll
    for (int nt = 0; nt < 4; nt++) {
        const int d = nt * 8 + 2 * t;
        if (r0 < 49)
            *(float2*)&outp[((size_t)b * 49 + r0) * DIMC + h * HD + d]
                = make_float2(o[nt][0], o[nt][1]);
        if (r0 + 8 < 49)
            *(float2*)&outp[((size_t)b * 49 + r0 + 8) * DIMC + h * HD + d]
                = make_float2(o[nt][2], o[nt][3]);
    }
}

// ---------------------------------------------------------------------------
extern "C" void kernel_launch(void* const* d_in, const int* in_sizes, int n_in,
                              void* d_out, int out_size)
{
    const float* x          = (const float*)d_in[0];
    const float* mask       = (const float*)d_in[1];
    const float* qkv_w      = (const float*)d_in[2];
    const float* qkv_b      = (const float*)d_in[3];
    const float* proj_w     = (const float*)d_in[4];
    const float* proj_b     = (const float*)d_in[5];
    const float* bias_table = (const float*)d_in[6];
    const int*   rel_index  = (const int*)d_in[7];
    float*       out        = (float*)d_out;

    float *qkvbuf = nullptr, *attbuf = nullptr;
    cudaGetSymbolAddress((void**)&qkvbuf, g_qkv);
    cudaGetSymbolAddress((void**)&attbuf, g_att);

    dim3 g1(M_TOTAL / 128, 384 / 64);
    gemm_tc_kernel<384><<<g1, 256>>>(x, qkv_w, qkv_b, qkvbuf);

    attn_tc_kernel<<<NB * HEADS, 128>>>(qkvbuf, mask, bias_table, rel_index, attbuf);

    dim3 g3(M_TOTAL / 128, DIMC / 64);
    gemm_tc_kernel<DIMC><<<g3, 256>>>(attbuf, proj_w, proj_b, out);
}

// round 4
// speedup vs baseline: 3.4002x; 1.5318x over previous
#include <cuda_runtime.h>
#include <math.h>
#include <stdint.h>

// Problem constants
#define DIMC   128
#define NWIN   49
#define HEADS  4
#define HD     32
#define NB     4096
#define M_TOTAL (NB * NWIN)        // 200704 = 1568 * 128

// Scratch (allocation-free rule: static device globals)
__device__ float g_qkv[(size_t)NB * NWIN * 384];   // [M, 384] : q|k|v per row
__device__ float g_att[(size_t)NB * NWIN * DIMC];  // [M, 128] : attention output
__device__ float g_comb[4 * 64 * 49 * 56];         // bias+mask, [h][wm][i][j(pad56)]

__device__ __forceinline__ float to_tf32(float x) {
    float r;
    asm("cvt.rna.tf32.f32 %0, %1;" : "=f"(r) : "f"(x));
    return r;
}
// round-to-nearest tf32 as raw bits: +half-ulp of the 13 truncated bits;
// the tensor core truncates the low 13 bits, so this equals cvt.rna.
__device__ __forceinline__ uint32_t rna_bits(float x) {
    return __float_as_uint(x) + 0x1000u;
}

__device__ __forceinline__ void mma_tf32(float c[4], const uint32_t a[4],
                                         uint32_t b0, uint32_t b1) {
    asm volatile(
        "mma.sync.aligned.m16n8k8.row.col.f32.tf32.tf32.f32 "
        "{%0,%1,%2,%3}, {%4,%5,%6,%7}, {%8,%9}, {%0,%1,%2,%3};"
        : "+f"(c[0]), "+f"(c[1]), "+f"(c[2]), "+f"(c[3])
        : "r"(a[0]), "r"(a[1]), "r"(a[2]), "r"(a[3]), "r"(b0), "r"(b1));
}

#define CP_ASYNC16(dst, src) \
    asm volatile("cp.async.ca.shared.global [%0], [%1], 16;" :: "r"(dst), "l"(src))
#define CP_COMMIT() asm volatile("cp.async.commit_group;")

// ---------------------------------------------------------------------------
// tf32 tensor-core GEMM v2: C[M][NC] = A[M][128] * W[NC][128]^T + bias
// Block tile 128x128, 256 threads = 8 warps (2m x 4n), warp tile 64x32
// (4x4 m16n8k8). K chunked by 16, cp.async double-buffered staging into
// plain row-major smem (row stride 20 floats: fragment LDS.32 conflict-free,
// rows 16B aligned for cp.async). tf32 RNA rounding applied at fragment load
// via +0x1000 bit trick.
// ---------------------------------------------------------------------------
template<int NC>
__global__ __launch_bounds__(256, 2) void gemm_tc2_kernel(
    const float* __restrict__ A, const float* __restrict__ W,
    const float* __restrict__ bias, float* __restrict__ C)
{
    __shared__ float As[2][128][20];
    __shared__ float Ws[2][128][20];

    const int tid  = threadIdx.x;
    const int lane = tid & 31;
    const int warp = tid >> 5;
    const int wm   = warp & 1;           // 2 warps in m
    const int wn   = warp >> 1;          // 4 warps in n
    const int g    = lane >> 2;
    const int t    = lane & 3;
    const long m0  = (long)blockIdx.x * 128;
    const int  n0  = blockIdx.y * 128;

    // staging map: each thread moves 2 x 16B for A and 2 x 16B for W per chunk
    const int srow = tid >> 2;           // 0..63
    const int sf   = tid & 3;            // 16B segment in the 64B chunk row
    const float* gA = A + (m0 + srow) * 128 + sf * 4;
    const float* gW = W + ((size_t)n0 + srow) * 128 + sf * 4;
    const uint32_t sA = (uint32_t)__cvta_generic_to_shared(&As[0][srow][sf * 4]);
    const uint32_t sW = (uint32_t)__cvta_generic_to_shared(&Ws[0][srow][sf * 4]);
    const uint32_t BUFB = 128 * 20 * 4;  // bytes per buffer
    const uint32_t ROW64 = 64 * 20 * 4;  // 64 rows in bytes

    float acc[4][4][4] = {};             // [mtile][ntile][frag]

    auto stage = [&](int kc, int buf) {
        const float* a = gA + kc * 16;
        const float* w = gW + kc * 16;
        CP_ASYNC16(sA + buf * BUFB,         a);
        CP_ASYNC16(sA + buf * BUFB + ROW64, a + 64 * 128);
        CP_ASYNC16(sW + buf * BUFB,         w);
        CP_ASYNC16(sW + buf * BUFB + ROW64, w + 64 * 128);
    };

    stage(0, 0); CP_COMMIT();
    stage(1, 1); CP_COMMIT();

    #pragma unroll
    for (int kc = 0; kc < 8; kc++) {
        if (kc < 7) asm volatile("cp.async.wait_group 1;");
        else        asm volatile("cp.async.wait_group 0;");
        __syncthreads();

        const int buf = kc & 1;
        #pragma unroll
        for (int s = 0; s < 2; s++) {
            const int off = s * 8;
            uint32_t a[4][4];
            #pragma unroll
            for (int mt = 0; mt < 4; mt++) {
                int r = wm * 64 + mt * 16 + g;
                a[mt][0] = rna_bits(As[buf][r][off + t]);
                a[mt][1] = rna_bits(As[buf][r + 8][off + t]);
                a[mt][2] = rna_bits(As[buf][r][off + t + 4]);
                a[mt][3] = rna_bits(As[buf][r + 8][off + t + 4]);
            }
            #pragma unroll
            for (int nt = 0; nt < 4; nt++) {
                int n = wn * 32 + nt * 8 + g;
                uint32_t b0 = rna_bits(Ws[buf][n][off + t]);
                uint32_t b1 = rna_bits(Ws[buf][n][off + t + 4]);
                #pragma unroll
                for (int mt = 0; mt < 4; mt++)
                    mma_tf32(acc[mt][nt], a[mt], b0, b1);
            }
        }
        __syncthreads();
        if (kc < 6) { stage(kc + 2, buf); CP_COMMIT(); }
    }

    // Epilogue: c0 (g,2t) c1 (g,2t+1) c2 (g+8,2t) c3 (g+8,2t+1)
    #pragma unroll
    for (int nt = 0; nt < 4; nt++) {
        int col = n0 + wn * 32 + nt * 8 + 2 * t;
        float b0 = bias[col], b1 = bias[col + 1];
        #pragma unroll
        for (int mt = 0; mt < 4; mt++) {
            long r = m0 + wm * 64 + mt * 16 + g;
            *(float2*)&C[r * NC + col] =
                make_float2(acc[mt][nt][0] + b0, acc[mt][nt][1] + b1);
            *(float2*)&C[(r + 8) * NC + col] =
                make_float2(acc[mt][nt][2] + b0, acc[mt][nt][3] + b1);
        }
    }
}

// ---------------------------------------------------------------------------
// Precompute combined rel-pos bias + shift mask: g_comb[h][wm][i][j(pad 56)]
// Pad cols j>=49 get -1e30 so softmax zeroes them.
// ---------------------------------------------------------------------------
__global__ void precomp_bias_mask(const float* __restrict__ mask,
                                  const float* __restrict__ bias_table,
                                  const int* __restrict__ rel_index)
{
    const int wm = blockIdx.x;   // 0..63
    const int h  = blockIdx.y;   // 0..3
    float* dst = g_comb + ((size_t)h * 64 + wm) * 49 * 56;
    for (int q = threadIdx.x; q < 49 * 56; q += blockDim.x) {
        int i = q / 56, j = q - i * 56;
        dst[q] = (j < 49)
            ? bias_table[rel_index[i * 49 + j] * HEADS + h]
              + mask[(size_t)wm * (NWIN * NWIN) + i * 49 + j]
            : -1e30f;
    }
}

// ---------------------------------------------------------------------------
// Tensor-core attention (round-3 structure; staging now reads g_comb
// linearly in float4 instead of triple-gathering per element).
// ---------------------------------------------------------------------------
__global__ __launch_bounds__(128) void attn_tc_kernel(
    const float* __restrict__ qkv, float* __restrict__ outp)
{
    __shared__ float Qs[64][40];
    __shared__ float Ks[56][40];
    __shared__ float Vt[32][72];
    __shared__ float Ss[64][72];

    const int tid  = threadIdx.x;
    const int lane = tid & 31;
    const int warp = tid >> 5;
    const int g = lane >> 2, t = lane & 3;
    const int b = blockIdx.x >> 2, h = blockIdx.x & 3;
    const float scale = 0.17677669529663687f;   // 32^-0.5

    // ---- stage Q (scaled), K, V^T with tf32 rounding + k-interleave ----
    for (int q = tid; q < 64 * 8; q += 128) {
        int i = q >> 3, f4 = q & 7;
        int base = (f4 >> 1) * 8 + (f4 & 1);
        if (i < 49) {
            size_t row = ((size_t)b * 49 + i) * 384 + h * 32 + f4 * 4;
            float4 vq = *(const float4*)(qkv + row);
            float4 vk = *(const float4*)(qkv + row + 128);
            float4 vv = *(const float4*)(qkv + row + 256);
            Qs[i][base + 0] = to_tf32(vq.x * scale);
            Qs[i][base + 2] = to_tf32(vq.y * scale);
            Qs[i][base + 4] = to_tf32(vq.z * scale);
            Qs[i][base + 6] = to_tf32(vq.w * scale);
            Ks[i][base + 0] = to_tf32(vk.x);
            Ks[i][base + 2] = to_tf32(vk.y);
            Ks[i][base + 4] = to_tf32(vk.z);
            Ks[i][base + 6] = to_tf32(vk.w);
            int pj = (i >> 3) * 8 + 2 * (i & 3) + ((i >> 2) & 1);
            Vt[f4 * 4 + 0][pj] = to_tf32(vv.x);
            Vt[f4 * 4 + 1][pj] = to_tf32(vv.y);
            Vt[f4 * 4 + 2][pj] = to_tf32(vv.z);
            Vt[f4 * 4 + 3][pj] = to_tf32(vv.w);
        } else {
            Qs[i][base] = Qs[i][base + 2] = Qs[i][base + 4] = Qs[i][base + 6] = 0.f;
            if (i < 56) {
                Ks[i][base] = Ks[i][base + 2] = Ks[i][base + 4] = Ks[i][base + 6] = 0.f;
                int pj = (i >> 3) * 8 + 2 * (i & 3) + ((i >> 2) & 1);
                Vt[f4 * 4 + 0][pj] = 0.f;
                Vt[f4 * 4 + 1][pj] = 0.f;
                Vt[f4 * 4 + 2][pj] = 0.f;
                Vt[f4 * 4 + 3][pj] = 0.f;
            }
        }
    }

    // ---- stage combined bias+mask (linear float4 copy) ----
    {
        const float4* comb = (const float4*)(g_comb
            + ((size_t)h * 64 + (b & 63)) * 49 * 56);
        for (int q = tid; q < 49 * 56 / 4; q += 128) {
            int i = q / 14, jf = q - i * 14;
            *(float4*)&Ss[i][jf * 4] = comb[q];
        }
        float4 z = make_float4(0.f, 0.f, 0.f, 0.f);
        for (int q = tid; q < 15 * 56 / 4; q += 128) {
            int i = 49 + q / 14, jf = q % 14;
            *(float4*)&Ss[i][jf * 4] = z;
        }
    }
    __syncthreads();

    // ---- S += (Q*scale) K^T ----
    const int r0 = warp * 16 + g;
    float c[7][4];
    #pragma unroll
    for (int nt = 0; nt < 7; nt++)
        #pragma unroll
        for (int e = 0; e < 4; e++) c[nt][e] = 0.f;

    #pragma unroll
    for (int s = 0; s < 4; s++) {
        const int off = s * 8 + 2 * t;
        uint32_t a[4];
        float2 f0 = *(const float2*)&Qs[r0][off];
        float2 f1 = *(const float2*)&Qs[r0 + 8][off];
        a[0] = __float_as_uint(f0.x); a[1] = __float_as_uint(f1.x);
        a[2] = __float_as_uint(f0.y); a[3] = __float_as_uint(f1.y);
        #pragma unroll
        for (int nt = 0; nt < 7; nt++) {
            float2 fb = *(const float2*)&Ks[nt * 8 + g][off];
            mma_tf32(c[nt], a, __float_as_uint(fb.x), __float_as_uint(fb.y));
        }
    }
    #pragma unroll
    for (int nt = 0; nt < 7; nt++) {
        int col = nt * 8 + 2 * t;
        Ss[r0][col]         += c[nt][0];
        Ss[r0][col + 1]     += c[nt][1];
        Ss[r0 + 8][col]     += c[nt][2];
        Ss[r0 + 8][col + 1] += c[nt][3];
    }
    __syncthreads();

    // ---- row softmax: 8 lanes per row; P written in-place, k-interleaved ----
    {
        const int l8  = tid & 7;
        const int rb  = tid >> 3;                       // 0..15
        const int pos = 2 * (l8 & 3) + (l8 >> 2);       // interleave of j&7
        #pragma unroll
        for (int rr = 0; rr < 4; rr++) {
            const int i = rb + rr * 16;
            float v[7];
            float mx = -1e30f;
            #pragma unroll
            for (int c2 = 0; c2 < 7; c2++) {
                v[c2] = Ss[i][l8 + 8 * c2];
                mx = fmaxf(mx, v[c2]);
            }
            mx = fmaxf(mx, __shfl_xor_sync(0xffffffffu, mx, 1, 8));
            mx = fmaxf(mx, __shfl_xor_sync(0xffffffffu, mx, 2, 8));
            mx = fmaxf(mx, __shfl_xor_sync(0xffffffffu, mx, 4, 8));
            float sum = 0.f;
            #pragma unroll
            for (int c2 = 0; c2 < 7; c2++) {
                v[c2] = __expf(v[c2] - mx);
                sum += v[c2];
            }
            sum += __shfl_xor_sync(0xffffffffu, sum, 1, 8);
            sum += __shfl_xor_sync(0xffffffffu, sum, 2, 8);
            sum += __shfl_xor_sync(0xffffffffu, sum, 4, 8);
            const float inv = 1.f / sum;
            #pragma unroll
            for (int c2 = 0; c2 < 7; c2++)
                Ss[i][c2 * 8 + pos] = to_tf32(v[c2] * inv);
        }
    }
    __syncthreads();

    // ---- O = P V ----
    float o[4][4];
    #pragma unroll
    for (int nt = 0; nt < 4; nt++)
        #pragma unroll
        for (int e = 0; e < 4; e++) o[nt][e] = 0.f;

    #pragma unroll
    for (int s = 0; s < 7; s++) {
        const int off = s * 8 + 2 * t;
        uint32_t a[4];
        float2 f0 = *(const float2*)&Ss[r0][off];
        float2 f1 = *(const float2*)&Ss[r0 + 8][off];
        a[0] = __float_as_uint(f0.x); a[1] = __float_as_uint(f1.x);
        a[2] = __float_as_uint(f0.y); a[3] = __float_as_uint(f1.y);
        #pragma unroll
        for (int nt = 0; nt < 4; nt++) {
            float2 fb = *(const float2*)&Vt[nt * 8 + g][off];
            mma_tf32(o[nt], a, __float_as_uint(fb.x), __float_as_uint(fb.y));
        }
    }

    #pragma unroll
    for (int nt = 0; nt < 4; nt++) {
        const int d = nt * 8 + 2 * t;
        if (r0 < 49)
            *(float2*)&outp[((size_t)b * 49 + r0) * DIMC + h * HD + d]
                = make_float2(o[nt][0], o[nt][1]);
        if (r0 + 8 < 49)
            *(float2*)&outp[((size_t)b * 49 + r0 + 8) * DIMC + h * HD + d]
                = make_float2(o[nt][2], o[nt][3]);
    }
}

// ---------------------------------------------------------------------------
extern "C" void kernel_launch(void* const* d_in, const int* in_sizes, int n_in,
                              void* d_out, int out_size)
{
    const float* x          = (const float*)d_in[0];
    const float* mask       = (const float*)d_in[1];
    const float* qkv_w      = (const float*)d_in[2];
    const float* qkv_b      = (const float*)d_in[3];
    const float* proj_w     = (const float*)d_in[4];
    const float* proj_b     = (const float*)d_in[5];
    const float* bias_table = (const float*)d_in[6];
    const int*   rel_index  = (const int*)d_in[7];
    float*       out        = (float*)d_out;

    float *qkvbuf = nullptr, *attbuf = nullptr;
    cudaGetSymbolAddress((void**)&qkvbuf, g_qkv);
    cudaGetSymbolAddress((void**)&attbuf, g_att);

    dim3 gp(64, 4);
    precomp_bias_mask<<<gp, 256>>>(mask, bias_table, rel_index);

    dim3 g1(M_TOTAL / 128, 384 / 128);
    gemm_tc2_kernel<384><<<g1, 256>>>(x, qkv_w, qkv_b, qkvbuf);

    attn_tc_kernel<<<NB * HEADS, 128>>>(qkvbuf, attbuf);

    dim3 g3(M_TOTAL / 128, DIMC / 128);
    gemm_tc2_kernel<DIMC><<<g3, 256>>>(attbuf, proj_w, proj_b, out);
}

// round 5
// speedup vs baseline: 3.9514x; 1.1621x over previous
#include <cuda_runtime.h>
#include <math.h>
#include <stdint.h>

// Problem constants
#define DIMC   128
#define NWIN   49
#define HEADS  4
#define HD     32
#define NB     4096
#define M_TOTAL (NB * NWIN)        // 200704 = 1568 * 128

// Scratch (allocation-free rule: static device globals)
__device__ float g_qkv[(size_t)NB * NWIN * 384];   // [M, 384] : q|k|v per row
__device__ float g_att[(size_t)NB * NWIN * DIMC];  // [M, 128] : attention output
__device__ float g_comb[4 * 64 * 49 * 56];         // bias+mask, [h][wm][i][j(pad56)]

__device__ __forceinline__ float to_tf32(float x) {
    float r;
    asm("cvt.rna.tf32.f32 %0, %1;" : "=f"(r) : "f"(x));
    return r;
}
// round-to-nearest tf32 as raw bits (tensor core truncates low 13 bits)
__device__ __forceinline__ uint32_t rna_bits(float x) {
    return __float_as_uint(x) + 0x1000u;
}

__device__ __forceinline__ void mma_tf32(float c[4], const uint32_t a[4],
                                         uint32_t b0, uint32_t b1) {
    asm volatile(
        "mma.sync.aligned.m16n8k8.row.col.f32.tf32.tf32.f32 "
        "{%0,%1,%2,%3}, {%4,%5,%6,%7}, {%8,%9}, {%0,%1,%2,%3};"
        : "+f"(c[0]), "+f"(c[1]), "+f"(c[2]), "+f"(c[3])
        : "r"(a[0]), "r"(a[1]), "r"(a[2]), "r"(a[3]), "r"(b0), "r"(b1));
}

#define CP_ASYNC16(dst, src) \
    asm volatile("cp.async.ca.shared.global [%0], [%1], 16;" :: "r"(dst), "l"(src))
#define CP_COMMIT() asm volatile("cp.async.commit_group;")

// ---------------------------------------------------------------------------
// tf32 GEMM v3: C[M][NC] = A[M][128] * W[NC][128]^T + bias
// 128x128 block tile, 8 warps (2m x 4n), warp tile 64x32, K chunks of 16.
// 3-stage cp.async ring in dynamic smem -> ONE __syncthreads per chunk
// (staged buffer is never the one being read). Row stride 20 floats keeps
// fragment LDS.32 conflict-free; tf32 RNA applied at fragment load.
// ---------------------------------------------------------------------------
#define GEMM_SMEM_BYTES (6 * 128 * 20 * 4)   // 3 bufs x (A + W)

template<int NC>
__global__ __launch_bounds__(256, 2) void gemm_tc3_kernel(
    const float* __restrict__ A, const float* __restrict__ W,
    const float* __restrict__ bias, float* __restrict__ C)
{
    extern __shared__ float sm[];            // [3][128][20] A, then [3][128][20] W

    const int tid  = threadIdx.x;
    const int lane = tid & 31;
    const int warp = tid >> 5;
    const int wm   = warp & 1;
    const int wn   = warp >> 1;
    const int g    = lane >> 2;
    const int t    = lane & 3;
    const long m0  = (long)blockIdx.x * 128;
    const int  n0  = blockIdx.y * 128;

    const int srow = tid >> 2;               // 0..63
    const int sf   = tid & 3;
    const float* gA = A + (m0 + srow) * 128 + sf * 4;
    const float* gW = W + ((size_t)n0 + srow) * 128 + sf * 4;
    const uint32_t sbase = (uint32_t)__cvta_generic_to_shared(sm);
    const uint32_t sA = sbase + (srow * 20 + sf * 4) * 4;
    const uint32_t sW = sA + 3 * 10240;
    const uint32_t BUFB  = 10240;            // 128*20*4
    const uint32_t ROW64 = 64 * 20 * 4;

    auto stage = [&](int kc, int buf) {
        const float* a = gA + kc * 16;
        const float* w = gW + kc * 16;
        CP_ASYNC16(sA + buf * BUFB,         a);
        CP_ASYNC16(sA + buf * BUFB + ROW64, a + 64 * 128);
        CP_ASYNC16(sW + buf * BUFB,         w);
        CP_ASYNC16(sW + buf * BUFB + ROW64, w + 64 * 128);
    };

    float acc[4][4][4] = {};

    stage(0, 0); CP_COMMIT();
    stage(1, 1); CP_COMMIT();

    #pragma unroll
    for (int kc = 0; kc < 8; kc++) {
        if (kc < 7) asm volatile("cp.async.wait_group 1;");
        else        asm volatile("cp.async.wait_group 0;");
        __syncthreads();
        if (kc < 6) { stage(kc + 2, (kc + 2) % 3); CP_COMMIT(); }

        const float* Ab = sm + (kc % 3) * 2560;
        const float* Wb = Ab + 3 * 2560;

        #pragma unroll
        for (int s = 0; s < 2; s++) {
            const int off = s * 8;
            uint32_t a[4][4];
            #pragma unroll
            for (int mt = 0; mt < 4; mt++) {
                int r = wm * 64 + mt * 16 + g;
                a[mt][0] = rna_bits(Ab[r * 20 + off + t]);
                a[mt][1] = rna_bits(Ab[(r + 8) * 20 + off + t]);
                a[mt][2] = rna_bits(Ab[r * 20 + off + t + 4]);
                a[mt][3] = rna_bits(Ab[(r + 8) * 20 + off + t + 4]);
            }
            #pragma unroll
            for (int nt = 0; nt < 4; nt++) {
                int n = wn * 32 + nt * 8 + g;
                uint32_t b0 = rna_bits(Wb[n * 20 + off + t]);
                uint32_t b1 = rna_bits(Wb[n * 20 + off + t + 4]);
                #pragma unroll
                for (int mt = 0; mt < 4; mt++)
                    mma_tf32(acc[mt][nt], a[mt], b0, b1);
            }
        }
    }

    #pragma unroll
    for (int nt = 0; nt < 4; nt++) {
        int col = n0 + wn * 32 + nt * 8 + 2 * t;
        float b0 = bias[col], b1 = bias[col + 1];
        #pragma unroll
        for (int mt = 0; mt < 4; mt++) {
            long r = m0 + wm * 64 + mt * 16 + g;
            *(float2*)&C[r * NC + col] =
                make_float2(acc[mt][nt][0] + b0, acc[mt][nt][1] + b1);
            *(float2*)&C[(r + 8) * NC + col] =
                make_float2(acc[mt][nt][2] + b0, acc[mt][nt][3] + b1);
        }
    }
}

// ---------------------------------------------------------------------------
// Precompute combined rel-pos bias + shift mask: g_comb[h][wm][i][j(pad 56)]
// ---------------------------------------------------------------------------
__global__ void precomp_bias_mask(const float* __restrict__ mask,
                                  const float* __restrict__ bias_table,
                                  const int* __restrict__ rel_index)
{
    const int wm = blockIdx.x;   // 0..63
    const int h  = blockIdx.y;   // 0..3
    float* dst = g_comb + ((size_t)h * 64 + wm) * 49 * 56;
    for (int q = threadIdx.x; q < 49 * 56; q += blockDim.x) {
        int i = q / 56, j = q - i * 56;
        dst[q] = (j < 49)
            ? bias_table[rel_index[i * 49 + j] * HEADS + h]
              + mask[(size_t)wm * (NWIN * NWIN) + i * 49 + j]
            : -1e30f;
    }
}

// ---------------------------------------------------------------------------
// Attention v3. Block = (window b, head h), 128 threads = 4 warps.
// QK accumulators initialized straight from g_comb (L2-resident);
// softmax fully in registers (rows live in 4 lanes -> shfl_xor 1,2);
// only P goes through smem (k-interleaved) for the PV A-fragments, which
// the SAME warp reads -> one __syncthreads + one __syncwarp total.
// ---------------------------------------------------------------------------
__global__ __launch_bounds__(128) void attn_tc_kernel(
    const float* __restrict__ qkv, float* __restrict__ outp)
{
    __shared__ float Qs[64][40];
    __shared__ float Ks[56][40];
    __shared__ float Vt[32][72];
    __shared__ float Ps[64][72];

    const int tid  = threadIdx.x;
    const int lane = tid & 31;
    const int warp = tid >> 5;
    const int g = lane >> 2, t = lane & 3;
    const int b = blockIdx.x >> 2, h = blockIdx.x & 3;
    const float scale = 0.17677669529663687f;   // 32^-0.5

    // ---- stage Q (scaled), K, V^T with tf32 rounding + k-interleave ----
    for (int q = tid; q < 64 * 8; q += 128) {
        int i = q >> 3, f4 = q & 7;
        int base = (f4 >> 1) * 8 + (f4 & 1);
        if (i < 49) {
            size_t row = ((size_t)b * 49 + i) * 384 + h * 32 + f4 * 4;
            float4 vq = *(const float4*)(qkv + row);
            float4 vk = *(const float4*)(qkv + row + 128);
            float4 vv = *(const float4*)(qkv + row + 256);
            Qs[i][base + 0] = to_tf32(vq.x * scale);
            Qs[i][base + 2] = to_tf32(vq.y * scale);
            Qs[i][base + 4] = to_tf32(vq.z * scale);
            Qs[i][base + 6] = to_tf32(vq.w * scale);
            Ks[i][base + 0] = to_tf32(vk.x);
            Ks[i][base + 2] = to_tf32(vk.y);
            Ks[i][base + 4] = to_tf32(vk.z);
            Ks[i][base + 6] = to_tf32(vk.w);
            int pj = (i >> 3) * 8 + 2 * (i & 3) + ((i >> 2) & 1);
            Vt[f4 * 4 + 0][pj] = to_tf32(vv.x);
            Vt[f4 * 4 + 1][pj] = to_tf32(vv.y);
            Vt[f4 * 4 + 2][pj] = to_tf32(vv.z);
            Vt[f4 * 4 + 3][pj] = to_tf32(vv.w);
        } else {
            Qs[i][base] = Qs[i][base + 2] = Qs[i][base + 4] = Qs[i][base + 6] = 0.f;
            if (i < 56) {
                Ks[i][base] = Ks[i][base + 2] = Ks[i][base + 4] = Ks[i][base + 6] = 0.f;
                int pj = (i >> 3) * 8 + 2 * (i & 3) + ((i >> 2) & 1);
                Vt[f4 * 4 + 0][pj] = 0.f;
                Vt[f4 * 4 + 1][pj] = 0.f;
                Vt[f4 * 4 + 2][pj] = 0.f;
                Vt[f4 * 4 + 3][pj] = 0.f;
            }
        }
    }

    // ---- init S accumulators from combined bias+mask (global, L2-hot) ----
    const int r0 = warp * 16 + g;
    const float* comb = g_comb + ((size_t)h * 64 + (b & 63)) * 49 * 56;
    float c[7][4];
    #pragma unroll
    for (int nt = 0; nt < 7; nt++) {
        const int col = nt * 8 + 2 * t;
        if (r0 < 49) {
            float2 f = *(const float2*)&comb[r0 * 56 + col];
            c[nt][0] = f.x; c[nt][1] = f.y;
        } else { c[nt][0] = 0.f; c[nt][1] = 0.f; }
        if (r0 + 8 < 49) {
            float2 f = *(const float2*)&comb[(r0 + 8) * 56 + col];
            c[nt][2] = f.x; c[nt][3] = f.y;
        } else { c[nt][2] = 0.f; c[nt][3] = 0.f; }
    }
    __syncthreads();

    // ---- S += (Q*scale) K^T ----
    #pragma unroll
    for (int s = 0; s < 4; s++) {
        const int off = s * 8 + 2 * t;
        uint32_t a[4];
        float2 f0 = *(const float2*)&Qs[r0][off];
        float2 f1 = *(const float2*)&Qs[r0 + 8][off];
        a[0] = __float_as_uint(f0.x); a[1] = __float_as_uint(f1.x);
        a[2] = __float_as_uint(f0.y); a[3] = __float_as_uint(f1.y);
        #pragma unroll
        for (int nt = 0; nt < 7; nt++) {
            float2 fb = *(const float2*)&Ks[nt * 8 + g][off];
            mma_tf32(c[nt], a, __float_as_uint(fb.x), __float_as_uint(fb.y));
        }
    }

    // ---- softmax in registers (row r0 in c[][0..1], row r0+8 in c[][2..3]) ----
    {
        float mx0 = -1e30f, mx1 = -1e30f;
        #pragma unroll
        for (int nt = 0; nt < 7; nt++) {
            mx0 = fmaxf(mx0, fmaxf(c[nt][0], c[nt][1]));
            mx1 = fmaxf(mx1, fmaxf(c[nt][2], c[nt][3]));
        }
        mx0 = fmaxf(mx0, __shfl_xor_sync(0xffffffffu, mx0, 1));
        mx0 = fmaxf(mx0, __shfl_xor_sync(0xffffffffu, mx0, 2));
        mx1 = fmaxf(mx1, __shfl_xor_sync(0xffffffffu, mx1, 1));
        mx1 = fmaxf(mx1, __shfl_xor_sync(0xffffffffu, mx1, 2));
        float s0 = 0.f, s1 = 0.f;
        #pragma unroll
        for (int nt = 0; nt < 7; nt++) {
            c[nt][0] = __expf(c[nt][0] - mx0);
            c[nt][1] = __expf(c[nt][1] - mx0);
            c[nt][2] = __expf(c[nt][2] - mx1);
            c[nt][3] = __expf(c[nt][3] - mx1);
            s0 += c[nt][0] + c[nt][1];
            s1 += c[nt][2] + c[nt][3];
        }
        s0 += __shfl_xor_sync(0xffffffffu, s0, 1);
        s0 += __shfl_xor_sync(0xffffffffu, s0, 2);
        s1 += __shfl_xor_sync(0xffffffffu, s1, 1);
        s1 += __shfl_xor_sync(0xffffffffu, s1, 2);
        const float i0 = 1.f / s0, i1 = 1.f / s1;

        // write P (k-interleaved): col c in 0..7 -> pos 2*(c&3) + (c>>2)
        const int pos0 = 2 * ((2 * t) & 3) + ((2 * t) >> 2);
        const int pos1 = 2 * ((2 * t + 1) & 3) + ((2 * t + 1) >> 2);
        #pragma unroll
        for (int nt = 0; nt < 7; nt++) {
            Ps[r0][nt * 8 + pos0]     = to_tf32(c[nt][0] * i0);
            Ps[r0][nt * 8 + pos1]     = to_tf32(c[nt][1] * i0);
            Ps[r0 + 8][nt * 8 + pos0] = to_tf32(c[nt][2] * i1);
            Ps[r0 + 8][nt * 8 + pos1] = to_tf32(c[nt][3] * i1);
        }
    }
    __syncwarp();

    // ---- O = P V ----
    float o[4][4];
    #pragma unroll
    for (int nt = 0; nt < 4; nt++)
        #pragma unroll
        for (int e = 0; e < 4; e++) o[nt][e] = 0.f;

    #pragma unroll
    for (int s = 0; s < 7; s++) {
        const int off = s * 8 + 2 * t;
        uint32_t a[4];
        float2 f0 = *(const float2*)&Ps[r0][off];
        float2 f1 = *(const float2*)&Ps[r0 + 8][off];
        a[0] = __float_as_uint(f0.x); a[1] = __float_as_uint(f1.x);
        a[2] = __float_as_uint(f0.y); a[3] = __float_as_uint(f1.y);
        #pragma unroll
        for (int nt = 0; nt < 4; nt++) {
            float2 fb = *(const float2*)&Vt[nt * 8 + g][off];
            mma_tf32(o[nt], a, __float_as_uint(fb.x), __float_as_uint(fb.y));
        }
    }

    #pragma unroll
    for (int nt = 0; nt < 4; nt++) {
        const int d = nt * 8 + 2 * t;
        if (r0 < 49)
            *(float2*)&outp[((size_t)b * 49 + r0) * DIMC + h * HD + d]
                = make_float2(o[nt][0], o[nt][1]);
        if (r0 + 8 < 49)
            *(float2*)&outp[((size_t)b * 49 + r0 + 8) * DIMC + h * HD + d]
                = make_float2(o[nt][2], o[nt][3]);
    }
}

// ---------------------------------------------------------------------------
extern "C" void kernel_launch(void* const* d_in, const int* in_sizes, int n_in,
                              void* d_out, int out_size)
{
    const float* x          = (const float*)d_in[0];
    const float* mask       = (const float*)d_in[1];
    const float* qkv_w      = (const float*)d_in[2];
    const float* qkv_b      = (const float*)d_in[3];
    const float* proj_w     = (const float*)d_in[4];
    const float* proj_b     = (const float*)d_in[5];
    const float* bias_table = (const float*)d_in[6];
    const int*   rel_index  = (const int*)d_in[7];
    float*       out        = (float*)d_out;

    float *qkvbuf = nullptr, *attbuf = nullptr;
    cudaGetSymbolAddress((void**)&qkvbuf, g_qkv);
    cudaGetSymbolAddress((void**)&attbuf, g_att);

    cudaFuncSetAttribute(gemm_tc3_kernel<384>,
                         cudaFuncAttributeMaxDynamicSharedMemorySize, GEMM_SMEM_BYTES);
    cudaFuncSetAttribute(gemm_tc3_kernel<DIMC>,
                         cudaFuncAttributeMaxDynamicSharedMemorySize, GEMM_SMEM_BYTES);

    dim3 gp(64, 4);
    precomp_bias_mask<<<gp, 256>>>(mask, bias_table, rel_index);

    dim3 g1(M_TOTAL / 128, 384 / 128);
    gemm_tc3_kernel<384><<<g1, 256, GEMM_SMEM_BYTES>>>(x, qkv_w, qkv_b, qkvbuf);

    attn_tc_kernel<<<NB * HEADS, 128>>>(qkvbuf, attbuf);

    dim3 g3(M_TOTAL / 128, DIMC / 128);
    gemm_tc3_kernel<DIMC><<<g3, 256, GEMM_SMEM_BYTES>>>(attbuf, proj_w, proj_b, out);
}